// round 2
// baseline (speedup 1.0000x reference)
#include <cuda_runtime.h>
#include <cuda_bf16.h>
#include <math.h>

#define HID 128
#define MAXN 50000

// ---------------- scratch (device globals: no allocation allowed) ----------------
__device__ float g_deg[MAXN];
__device__ float g_dinv[MAXN];
__device__ float g_aggr[(size_t)MAXN * HID];
__device__ float g_h1[(size_t)MAXN * HID];
__device__ float g_h2[(size_t)MAXN * HID];

// ---------------- utility kernels ----------------
__global__ void zero_kernel(float* __restrict__ p, size_t n) {
    size_t i = (size_t)blockIdx.x * blockDim.x + threadIdx.x;
    size_t stride = (size_t)gridDim.x * blockDim.x;
    for (; i < n; i += stride) p[i] = 0.0f;
}

__global__ void count_deg_kernel(const int* __restrict__ dst, float* __restrict__ deg, int E) {
    int e = blockIdx.x * blockDim.x + threadIdx.x;
    if (e < E) atomicAdd(&deg[dst[e]], 1.0f);
}

__global__ void finalize_deg_kernel(const float* __restrict__ deg, float* __restrict__ dinv, int n) {
    int i = blockIdx.x * blockDim.x + threadIdx.x;
    if (i < n) dinv[i] = 1.0f / fmaxf(deg[i], 1.0f);
}

// warp per edge: gather 128-float source row (float4/lane), scatter-add to dst row
__global__ void scatter_kernel(const float* __restrict__ feat,
                               const int* __restrict__ src,
                               const int* __restrict__ dst,
                               float* __restrict__ aggr, int E) {
    int w = (blockIdx.x * blockDim.x + threadIdx.x) >> 5;
    int lane = threadIdx.x & 31;
    if (w >= E) return;
    int s = src[w];
    int d = dst[w];
    float4 v = ((const float4*)(feat + (size_t)s * HID))[lane];
    float* o = aggr + (size_t)d * HID + lane * 4;
    atomicAdd(o + 0, v.x);
    atomicAdd(o + 1, v.y);
    atomicAdd(o + 2, v.z);
    atomicAdd(o + 3, v.w);
}

// ---------------- fused SAGE layer: out = act( (aggr*dinv)@Wl + x@Wr + b ) ----------------
// blockDim = 128 (one thread per output column). W staged in dynamic shared (132KB).
#define NODES_PER_BLOCK 32
#define LAYER_SMEM (2 * HID * HID * 4 + 8 * HID * 4)

__global__ void __launch_bounds__(128, 1)
layer_kernel(const float* __restrict__ aggr, const float* __restrict__ dinv,
             const float* __restrict__ xin, const float* __restrict__ Wl,
             const float* __restrict__ Wr, const float* __restrict__ bias,
             float* __restrict__ out, int n, int do_relu) {
    extern __shared__ float sh[];
    float* sWl = sh;                       // 128*128
    float* sWr = sh + HID * HID;           // 128*128
    float* sA  = sh + 2 * HID * HID;       // 4*128
    float* sX  = sA + 4 * HID;             // 4*128

    int tid = threadIdx.x;  // output column j
    #pragma unroll 4
    for (int i = tid; i < HID * HID; i += 128) {
        sWl[i] = Wl[i];
        sWr[i] = Wr[i];
    }
    float bj = bias[tid];
    int base = blockIdx.x * NODES_PER_BLOCK;

    for (int g = 0; g < NODES_PER_BLOCK; g += 4) {
        int n0 = base + g;
        __syncthreads();  // covers W staging on first iter + prior compute
        #pragma unroll
        for (int i = 0; i < 4; i++) {
            int node = n0 + i;
            if (node < n) {
                sA[i * HID + tid] = aggr[(size_t)node * HID + tid] * dinv[node];
                sX[i * HID + tid] = xin[(size_t)node * HID + tid];
            } else {
                sA[i * HID + tid] = 0.0f;
                sX[i * HID + tid] = 0.0f;
            }
        }
        __syncthreads();

        float acc0 = bj, acc1 = bj, acc2 = bj, acc3 = bj;
        const float4* a0 = (const float4*)(sA + 0 * HID);
        const float4* a1 = (const float4*)(sA + 1 * HID);
        const float4* a2 = (const float4*)(sA + 2 * HID);
        const float4* a3 = (const float4*)(sA + 3 * HID);
        const float4* x0 = (const float4*)(sX + 0 * HID);
        const float4* x1 = (const float4*)(sX + 1 * HID);
        const float4* x2 = (const float4*)(sX + 2 * HID);
        const float4* x3 = (const float4*)(sX + 3 * HID);

        #pragma unroll 8
        for (int k4 = 0; k4 < HID / 4; k4++) {
            float4 A0 = a0[k4], A1 = a1[k4], A2 = a2[k4], A3 = a3[k4];
            float4 X0 = x0[k4], X1 = x1[k4], X2 = x2[k4], X3 = x3[k4];
            int kb = k4 * 4;
            #pragma unroll
            for (int kk = 0; kk < 4; kk++) {
                float wl = sWl[(kb + kk) * HID + tid];
                float wr = sWr[(kb + kk) * HID + tid];
                float av0 = (kk == 0) ? A0.x : (kk == 1) ? A0.y : (kk == 2) ? A0.z : A0.w;
                float av1 = (kk == 0) ? A1.x : (kk == 1) ? A1.y : (kk == 2) ? A1.z : A1.w;
                float av2 = (kk == 0) ? A2.x : (kk == 1) ? A2.y : (kk == 2) ? A2.z : A2.w;
                float av3 = (kk == 0) ? A3.x : (kk == 1) ? A3.y : (kk == 2) ? A3.z : A3.w;
                float xv0 = (kk == 0) ? X0.x : (kk == 1) ? X0.y : (kk == 2) ? X0.z : X0.w;
                float xv1 = (kk == 0) ? X1.x : (kk == 1) ? X1.y : (kk == 2) ? X1.z : X1.w;
                float xv2 = (kk == 0) ? X2.x : (kk == 1) ? X2.y : (kk == 2) ? X2.z : X2.w;
                float xv3 = (kk == 0) ? X3.x : (kk == 1) ? X3.y : (kk == 2) ? X3.z : X3.w;
                acc0 = fmaf(av0, wl, acc0); acc0 = fmaf(xv0, wr, acc0);
                acc1 = fmaf(av1, wl, acc1); acc1 = fmaf(xv1, wr, acc1);
                acc2 = fmaf(av2, wl, acc2); acc2 = fmaf(xv2, wr, acc2);
                acc3 = fmaf(av3, wl, acc3); acc3 = fmaf(xv3, wr, acc3);
            }
        }
        if (do_relu) {
            acc0 = fmaxf(acc0, 0.0f); acc1 = fmaxf(acc1, 0.0f);
            acc2 = fmaxf(acc2, 0.0f); acc3 = fmaxf(acc3, 0.0f);
        }
        if (n0 + 0 < n) out[(size_t)(n0 + 0) * HID + tid] = acc0;
        if (n0 + 1 < n) out[(size_t)(n0 + 1) * HID + tid] = acc1;
        if (n0 + 2 < n) out[(size_t)(n0 + 2) * HID + tid] = acc2;
        if (n0 + 3 < n) out[(size_t)(n0 + 3) * HID + tid] = acc3;
    }
}

// ---------------- logits head: warp per node ----------------
__global__ void logits_kernel(const float* __restrict__ h, const float* __restrict__ Wout,
                              const float* __restrict__ bout, float* __restrict__ out, int n) {
    int w = (blockIdx.x * blockDim.x + threadIdx.x) >> 5;
    int lane = threadIdx.x & 31;
    if (w >= n) return;
    float4 v = ((const float4*)(h + (size_t)w * HID))[lane];
    int k = lane * 4;
    float s0 = v.x * Wout[(k + 0) * 2 + 0] + v.y * Wout[(k + 1) * 2 + 0] +
               v.z * Wout[(k + 2) * 2 + 0] + v.w * Wout[(k + 3) * 2 + 0];
    float s1 = v.x * Wout[(k + 0) * 2 + 1] + v.y * Wout[(k + 1) * 2 + 1] +
               v.z * Wout[(k + 2) * 2 + 1] + v.w * Wout[(k + 3) * 2 + 1];
    #pragma unroll
    for (int off = 16; off > 0; off >>= 1) {
        s0 += __shfl_xor_sync(0xFFFFFFFFu, s0, off);
        s1 += __shfl_xor_sync(0xFFFFFFFFu, s1, off);
    }
    if (lane == 0) {
        out[(size_t)w * 2 + 0] = s0 + bout[0];
        out[(size_t)w * 2 + 1] = s1 + bout[1];
    }
}

// ---------------- launch ----------------
extern "C" void kernel_launch(void* const* d_in, const int* in_sizes, int n_in,
                              void* d_out, int out_size) {
    const float* x    = (const float*)d_in[0];
    const int*   ei   = (const int*)d_in[1];   // JAX silently downcasts int64 -> int32
    const float* W1l  = (const float*)d_in[2];
    const float* W1r  = (const float*)d_in[3];
    const float* b1   = (const float*)d_in[4];
    const float* W2l  = (const float*)d_in[5];
    const float* W2r  = (const float*)d_in[6];
    const float* b2   = (const float*)d_in[7];
    const float* Wout = (const float*)d_in[8];
    const float* bout = (const float*)d_in[9];
    float* dout = (float*)d_out;

    int n = in_sizes[0] / HID;
    int E = in_sizes[1] / 2;
    const int* src = ei;
    const int* dst = ei + E;

    float *p_deg, *p_dinv, *p_aggr, *p_h1, *p_h2;
    cudaGetSymbolAddress((void**)&p_deg,  g_deg);
    cudaGetSymbolAddress((void**)&p_dinv, g_dinv);
    cudaGetSymbolAddress((void**)&p_aggr, g_aggr);
    cudaGetSymbolAddress((void**)&p_h1,   g_h1);
    cudaGetSymbolAddress((void**)&p_h2,   g_h2);

    cudaFuncSetAttribute(layer_kernel, cudaFuncAttributeMaxDynamicSharedMemorySize, LAYER_SMEM);

    // tuple output: logits [n*2] then h [n*128]
    float* hOut = ((size_t)out_size >= (size_t)n * (HID + 2)) ? (dout + (size_t)n * 2) : p_h2;

    size_t featN = (size_t)n * HID;

    // degree (once; same graph both layers)
    zero_kernel<<<256, 256>>>(p_deg, (size_t)n);
    count_deg_kernel<<<(E + 255) / 256, 256>>>(dst, p_deg, E);
    finalize_deg_kernel<<<(n + 255) / 256, 256>>>(p_deg, p_dinv, n);

    // ---- layer 1 ----
    zero_kernel<<<4096, 1024>>>(p_aggr, featN);
    scatter_kernel<<<(E * 32 + 255) / 256, 256>>>(x, src, dst, p_aggr, E);
    layer_kernel<<<(n + NODES_PER_BLOCK - 1) / NODES_PER_BLOCK, 128, LAYER_SMEM>>>(
        p_aggr, p_dinv, x, W1l, W1r, b1, p_h1, n, 1);

    // ---- layer 2 ----
    zero_kernel<<<4096, 1024>>>(p_aggr, featN);
    scatter_kernel<<<(E * 32 + 255) / 256, 256>>>(p_h1, src, dst, p_aggr, E);
    layer_kernel<<<(n + NODES_PER_BLOCK - 1) / NODES_PER_BLOCK, 128, LAYER_SMEM>>>(
        p_aggr, p_dinv, p_h1, W2l, W2r, b2, hOut, n, 1);

    // ---- head ----
    logits_kernel<<<(n * 32 + 255) / 256, 256>>>(hOut, Wout, bout, dout, n);
}

// round 3
// speedup vs baseline: 2.3470x; 2.3470x over previous
#include <cuda_runtime.h>
#include <cuda_bf16.h>
#include <math.h>

#define HID 128
#define MAXN 50000
#define MAXE 800000

// ---------------- scratch (device globals) ----------------
__device__ int   g_counts[MAXN + 1];
__device__ int   g_off[MAXN + 1];
__device__ int   g_cursor[MAXN];
__device__ int   g_esrc[MAXE];
__device__ float g_aggr[(size_t)MAXN * HID];
__device__ float g_h1[(size_t)MAXN * HID];
__device__ float g_h2[(size_t)MAXN * HID];

// ---------------- f32x2 packed-math macros ----------------
#define PACKF2(out, lo, hi) \
    asm("mov.b64 %0, {%1, %2};" : "=l"(out) : "f"(lo), "f"(hi))
#define UNPACKF2(lo, hi, v) \
    asm("mov.b64 {%0, %1}, %2;" : "=f"(lo), "=f"(hi) : "l"(v))
#define FMAF2(acc, a, b) \
    asm("fma.rn.f32x2 %0, %1, %2, %0;" : "+l"(acc) : "l"(a), "l"(b))

// ---------------- CSR build ----------------
__global__ void zero_int_kernel(int* __restrict__ p, int n) {
    int i = blockIdx.x * blockDim.x + threadIdx.x;
    if (i < n) p[i] = 0;
}

__global__ void hist_kernel(const int* __restrict__ dst, int* __restrict__ counts, int E) {
    int e = blockIdx.x * blockDim.x + threadIdx.x;
    if (e < E) atomicAdd(&counts[dst[e]], 1);
}

// single-block exclusive scan over counts[0..n) -> off[0..n], also copies to cursor
__global__ void scan_kernel(const int* __restrict__ counts, int* __restrict__ off,
                            int* __restrict__ cursor, int n) {
    __shared__ int part[1024];
    int tid = threadIdx.x;
    int chunk = (n + 1023) >> 10;
    int start = tid * chunk;
    int end = start + chunk; if (end > n) end = n;
    int s = 0;
    for (int i = start; i < end; i++) s += counts[i];
    part[tid] = s;
    __syncthreads();
    // Hillis-Steele inclusive scan
    for (int d = 1; d < 1024; d <<= 1) {
        int v = (tid >= d) ? part[tid - d] : 0;
        __syncthreads();
        part[tid] += v;
        __syncthreads();
    }
    int pre = (tid == 0) ? 0 : part[tid - 1];
    for (int i = start; i < end; i++) {
        off[i] = pre;
        cursor[i] = pre;
        pre += counts[i];
    }
    if (end == n) off[n] = pre;  // == E (benign multi-write of same value)
}

__global__ void fill_kernel(const int* __restrict__ src, const int* __restrict__ dst,
                            int* __restrict__ cursor, int* __restrict__ esrc, int E) {
    int e = blockIdx.x * blockDim.x + threadIdx.x;
    if (e < E) {
        int d = dst[e];
        int pos = atomicAdd(&cursor[d], 1);
        esrc[pos] = src[e];
    }
}

// ---------------- gather-aggregate (mean): warp per dst node ----------------
__global__ void gather_kernel(const float* __restrict__ feat, const int* __restrict__ esrc,
                              const int* __restrict__ off, float* __restrict__ aggr, int n) {
    int w = (blockIdx.x * blockDim.x + threadIdx.x) >> 5;
    int lane = threadIdx.x & 31;
    if (w >= n) return;
    int o0 = off[w], o1 = off[w + 1];
    const float4* f4 = (const float4*)feat;
    float4 a0 = {0.f, 0.f, 0.f, 0.f};
    float4 a1 = {0.f, 0.f, 0.f, 0.f};
    int k = o0;
    for (; k + 2 <= o1; k += 2) {
        int s0 = __ldg(esrc + k);
        int s1 = __ldg(esrc + k + 1);
        float4 v0 = f4[(size_t)s0 * 32 + lane];
        float4 v1 = f4[(size_t)s1 * 32 + lane];
        a0.x += v0.x; a0.y += v0.y; a0.z += v0.z; a0.w += v0.w;
        a1.x += v1.x; a1.y += v1.y; a1.z += v1.z; a1.w += v1.w;
    }
    if (k < o1) {
        int s = __ldg(esrc + k);
        float4 v = f4[(size_t)s * 32 + lane];
        a0.x += v.x; a0.y += v.y; a0.z += v.z; a0.w += v.w;
    }
    float inv = 1.0f / fmaxf((float)(o1 - o0), 1.0f);
    float4 r;
    r.x = (a0.x + a1.x) * inv;
    r.y = (a0.y + a1.y) * inv;
    r.z = (a0.z + a1.z) * inv;
    r.w = (a0.w + a1.w) * inv;
    ((float4*)aggr)[(size_t)w * 32 + lane] = r;
}

// ---------------- fused SAGE layer via f32x2 packed FFMA ----------------
// out[node][j] = relu( sum_{k<128} A[node][k]*Wl[k][j] + sum_{k<128} X[node][k]*Wr[k][j] + b[j] )
// A already mean-scaled. Combined K=256 GEMM, W=[Wl;Wr] in smem (128KB).
// 256 threads: 2 halves x 128 cols. Each half processes 8 nodes (4 f32x2 pairs).
#define SS_STRIDE 10  // floats per k row (8 used + 2 pad), keeps 8B alignment, 2-way STS conflict
#define LAYER_SMEM ((256 * 128 + 2 * 256 * SS_STRIDE) * 4)

__global__ void __launch_bounds__(256, 1)
layer_kernel(const float* __restrict__ A, const float* __restrict__ X,
             const float* __restrict__ Wl, const float* __restrict__ Wr,
             const float* __restrict__ bias, float* __restrict__ out, int n) {
    extern __shared__ float sh[];
    float* sW = sh;                     // [256][128], sW[k*128+j]
    float* sS = sh + 256 * 128;         // [2][256][SS_STRIDE]

    int tid = threadIdx.x;
    int hh = tid >> 7;          // half: 0/1
    int col = tid & 127;        // output column

    #pragma unroll 4
    for (int i = tid; i < 128 * 128; i += 256) {
        sW[i] = Wl[i];
        sW[128 * 128 + i] = Wr[i];
    }
    float bj = bias[col];
    unsigned long long b2;
    PACKF2(b2, bj, bj);

    float* sSh = sS + hh * 256 * SS_STRIDE;
    int nGroups = (n + 15) >> 4;

    for (int grp = blockIdx.x; grp < nGroups; grp += gridDim.x) {
        int nodeBase = grp * 16 + hh * 8;
        __syncthreads();
        // stage S = [A | X] for 8 nodes, pre-packed by node pairs along k rows
        #pragma unroll
        for (int i = 0; i < 8; i++) {
            int node = nodeBase + i;
            float va = 0.f, vx = 0.f;
            if (node < n) {
                va = A[(size_t)node * HID + col];
                vx = X[(size_t)node * HID + col];
            }
            sSh[col * SS_STRIDE + i] = va;
            sSh[(col + 128) * SS_STRIDE + i] = vx;
        }
        __syncthreads();

        unsigned long long acc0 = b2, acc1 = b2, acc2 = b2, acc3 = b2;
        #pragma unroll 4
        for (int k = 0; k < 256; k++) {
            float w = sW[k * 128 + col];
            unsigned long long w2;
            PACKF2(w2, w, w);
            const unsigned long long* row =
                reinterpret_cast<const unsigned long long*>(sSh + k * SS_STRIDE);
            unsigned long long p0 = row[0];
            unsigned long long p1 = row[1];
            unsigned long long p2 = row[2];
            unsigned long long p3 = row[3];
            FMAF2(acc0, p0, w2);
            FMAF2(acc1, p1, w2);
            FMAF2(acc2, p2, w2);
            FMAF2(acc3, p3, w2);
        }

        float v0, v1;
        #pragma unroll
        for (int p = 0; p < 4; p++) {
            unsigned long long a = (p == 0) ? acc0 : (p == 1) ? acc1 : (p == 2) ? acc2 : acc3;
            UNPACKF2(v0, v1, a);
            v0 = fmaxf(v0, 0.f);
            v1 = fmaxf(v1, 0.f);
            int n0 = nodeBase + p * 2;
            if (n0 < n)     out[(size_t)n0 * HID + col] = v0;
            if (n0 + 1 < n) out[(size_t)(n0 + 1) * HID + col] = v1;
        }
    }
}

// ---------------- logits head: warp per node ----------------
__global__ void logits_kernel(const float* __restrict__ h, const float* __restrict__ Wout,
                              const float* __restrict__ bout, float* __restrict__ out, int n) {
    int w = (blockIdx.x * blockDim.x + threadIdx.x) >> 5;
    int lane = threadIdx.x & 31;
    if (w >= n) return;
    float4 v = ((const float4*)(h + (size_t)w * HID))[lane];
    int k = lane * 4;
    float s0 = v.x * Wout[(k + 0) * 2 + 0] + v.y * Wout[(k + 1) * 2 + 0] +
               v.z * Wout[(k + 2) * 2 + 0] + v.w * Wout[(k + 3) * 2 + 0];
    float s1 = v.x * Wout[(k + 0) * 2 + 1] + v.y * Wout[(k + 1) * 2 + 1] +
               v.z * Wout[(k + 2) * 2 + 1] + v.w * Wout[(k + 3) * 2 + 1];
    #pragma unroll
    for (int off = 16; off > 0; off >>= 1) {
        s0 += __shfl_xor_sync(0xFFFFFFFFu, s0, off);
        s1 += __shfl_xor_sync(0xFFFFFFFFu, s1, off);
    }
    if (lane == 0) {
        out[(size_t)w * 2 + 0] = s0 + bout[0];
        out[(size_t)w * 2 + 1] = s1 + bout[1];
    }
}

// ---------------- launch ----------------
extern "C" void kernel_launch(void* const* d_in, const int* in_sizes, int n_in,
                              void* d_out, int out_size) {
    const float* x    = (const float*)d_in[0];
    const int*   ei   = (const int*)d_in[1];   // int32 on device
    const float* W1l  = (const float*)d_in[2];
    const float* W1r  = (const float*)d_in[3];
    const float* b1   = (const float*)d_in[4];
    const float* W2l  = (const float*)d_in[5];
    const float* W2r  = (const float*)d_in[6];
    const float* b2   = (const float*)d_in[7];
    const float* Wout = (const float*)d_in[8];
    const float* bout = (const float*)d_in[9];
    float* dout = (float*)d_out;

    int n = in_sizes[0] / HID;
    int E = in_sizes[1] / 2;
    const int* src = ei;
    const int* dst = ei + E;

    int *p_counts, *p_off, *p_cursor, *p_esrc;
    float *p_aggr, *p_h1, *p_h2;
    cudaGetSymbolAddress((void**)&p_counts, g_counts);
    cudaGetSymbolAddress((void**)&p_off,    g_off);
    cudaGetSymbolAddress((void**)&p_cursor, g_cursor);
    cudaGetSymbolAddress((void**)&p_esrc,   g_esrc);
    cudaGetSymbolAddress((void**)&p_aggr,   g_aggr);
    cudaGetSymbolAddress((void**)&p_h1,     g_h1);
    cudaGetSymbolAddress((void**)&p_h2,     g_h2);

    cudaFuncSetAttribute(layer_kernel, cudaFuncAttributeMaxDynamicSharedMemorySize, LAYER_SMEM);

    // tuple output: logits [n*2] then h [n*128]
    float* hOut = ((size_t)out_size >= (size_t)n * (HID + 2)) ? (dout + (size_t)n * 2) : p_h2;

    // ---- CSR build (once per call; same graph both layers) ----
    zero_int_kernel<<<(n + 255) / 256, 256>>>(p_counts, n);
    hist_kernel<<<(E + 255) / 256, 256>>>(dst, p_counts, E);
    scan_kernel<<<1, 1024>>>(p_counts, p_off, p_cursor, n);
    fill_kernel<<<(E + 255) / 256, 256>>>(src, dst, p_cursor, p_esrc, E);

    int gatherGrid = (n * 32 + 255) / 256;

    // ---- layer 1 ----
    gather_kernel<<<gatherGrid, 256>>>(x, p_esrc, p_off, p_aggr, n);
    layer_kernel<<<148, 256, LAYER_SMEM>>>(p_aggr, x, W1l, W1r, b1, p_h1, n);

    // ---- layer 2 ----
    gather_kernel<<<gatherGrid, 256>>>(p_h1, p_esrc, p_off, p_aggr, n);
    layer_kernel<<<148, 256, LAYER_SMEM>>>(p_aggr, p_h1, W2l, W2r, b2, hOut, n);

    // ---- head ----
    logits_kernel<<<(n * 32 + 255) / 256, 256>>>(hOut, Wout, bout, dout, n);
}